// round 6
// baseline (speedup 1.0000x reference)
#include <cuda_runtime.h>
#include <cuda_bf16.h>

// Box_diamond: two-layer soft-AND over 8-wide bins.
// out[b,p] = 1/(1 - log prod_m( (s_m - W2[p,m]) / s_m )),
// s_m = 1 - log prod_{l:|l-m|<=3} (1 - x[..]*W1[p,l-m]),  p = 4k+j
// W1[p,d]=sigmoid(d*(t2-d)) <=6e-6 for |d|>=4 -> truncated window.
// R6: zero staging / zero per-tile barriers. x loaded GMEM->regs (LDG.64,
// fully sector-efficient), W1 in regs, 2-tile intra-thread pipeline,
// direct coalesced streaming stores. f32x2 packed math.

#define D_TOT   4096
#define P_TOT   512
#define NTH     256

typedef unsigned long long u64;

#define ONE2     0x3F8000003F800000ULL  // {1.0f, 1.0f}
#define NEGLN2_2 0xBF317218BF317218ULL  // {-ln2, -ln2}

__device__ __forceinline__ u64 fma2(u64 a, u64 b, u64 c) {
    u64 d; asm("fma.rn.f32x2 %0, %1, %2, %3;" : "=l"(d) : "l"(a), "l"(b), "l"(c)); return d;
}
__device__ __forceinline__ u64 mul2(u64 a, u64 b) {
    u64 d; asm("mul.rn.f32x2 %0, %1, %2;" : "=l"(d) : "l"(a), "l"(b)); return d;
}
__device__ __forceinline__ u64 pack2(float lo, float hi) {
    u64 d; asm("mov.b64 %0, {%1, %2};" : "=l"(d) : "f"(lo), "f"(hi)); return d;
}
__device__ __forceinline__ void unpack2(float& lo, float& hi, u64 v) {
    asm("mov.b64 {%0, %1}, %2;" : "=f"(lo), "=f"(hi) : "l"(v));
}
__device__ __forceinline__ float frcp(float v) {
    float r; asm("rcp.approx.f32 %0, %1;" : "=f"(r) : "f"(v)); return r;
}
__device__ __forceinline__ float fsigmoid(float z) {
    return frcp(1.0f + __expf(-z));
}
__device__ __forceinline__ u64 ldg64(const float* p) {
    u64 v; asm("ld.global.nc.b64 %0, [%1];" : "=l"(v) : "l"(p)); return v;
}
__device__ __forceinline__ void st_stream_f2(float* p, float a, float b) {
    asm volatile("st.global.cs.v2.f32 [%0], {%1, %2};" :: "l"(p), "f"(a), "f"(b));
}

__device__ __forceinline__ void compute_tile(const u64* __restrict__ nx,
                                             const u64* __restrict__ w1r,
                                             const float (*w2s)[16],
                                             int sub, float* optr) {
    u64 num = ONE2, den = ONE2;
    #pragma unroll
    for (int m = 0; m < 8; m++) {
        const int lo = (m - 3 < 0) ? 0 : m - 3;
        const int hi = (m + 3 > 7) ? 7 : m + 3;
        u64 pr = fma2(nx[lo], w1r[lo - m + 3], ONE2);   // 1 - x*W1 (W1 negated)
        #pragma unroll
        for (int l = lo + 1; l <= hi; l++)
            pr = mul2(pr, fma2(nx[l], w1r[l - m + 3], ONE2));
        float a0, a1;
        unpack2(a0, a1, pr);
        u64 lg  = pack2(__log2f(a0), __log2f(a1));
        u64 w2v = *reinterpret_cast<const u64*>(&w2s[m][sub * 2]);  // 1 - W2
        num = mul2(num, fma2(lg, NEGLN2_2, w2v));   // s - W2
        den = mul2(den, fma2(lg, NEGLN2_2, ONE2));  // s
    }
    float n0, n1, d0, d1;
    unpack2(n0, n1, num);
    unpack2(d0, d1, den);
    const float LN2 = 0.6931471805599453f;
    float o0 = frcp(fmaf(-LN2, __log2f(n0) - __log2f(d0), 1.0f));
    float o1 = frcp(fmaf(-LN2, __log2f(n1) - __log2f(d1), 1.0f));
    st_stream_f2(optr, o0, o1);
}

__global__ __launch_bounds__(NTH, 3)
void box_diamond_kernel(const float* __restrict__ x,
                        const float* __restrict__ t0,
                        const float* __restrict__ t1,
                        const float* __restrict__ t2,
                        float* __restrict__ out) {
    __shared__ float w1s[7][16];   // -W1 [d+3][p_local]
    __shared__ float w2s[8][16];   // 1-W2 [m][p_local]

    const int tid   = threadIdx.x;
    const int by    = blockIdx.y;          // p-tile of 16
    const int pbase = by * 16;

    // thread mapping: lane = (b & 3)*8 + sub, sub = g*2 + jp
    const int w    = tid >> 5;
    const int lane = tid & 31;
    const int b_l  = w * 4 + (lane >> 3);  // 0..31 within tile
    const int sub  = lane & 7;             // p-pair index (p_local = 2*sub)
    const int g    = sub >> 1;             // 0..3
    const int jp   = sub & 1;

    const int brow0 = blockIdx.x * 64 + b_l;

    // ---- issue ALL x loads first (32 B/thread/tile, fly during table build) ----
    const float* xb0 = x + (size_t)brow0 * D_TOT + (by * 4 + g) * 32 + jp * 2;
    const float* xb1 = xb0 + (size_t)32 * D_TOT;

    u64 nx[8], ny[8];
    #pragma unroll
    for (int l = 0; l < 8; l++) nx[l] = ldg64(xb0 + l * 4);
    #pragma unroll
    for (int l = 0; l < 8; l++) ny[l] = ldg64(xb1 + l * 4);

    // ---- build tables (overlaps x-load flight) ----
    if (tid < 112) {              // -W1: 7d x 16p
        int d  = tid >> 4;
        int pl = tid & 15;
        float dd = (float)(d - 3);
        w1s[d][pl] = -fsigmoid(dd * (t2[pbase + pl] - dd));
    }
    if (tid < 128) {              // 1-W2: 8m x 16p
        int m  = tid >> 4;
        int pl = tid & 15;
        int p  = pbase + pl;
        float lf = (float)m;
        float z1 = (lf - t0[p]) * (t1[p] - lf);
        float z2 = (7.0f - t2[p] - lf) * lf;
        w2s[m][pl] = 1.0f - fsigmoid(z1) * fsigmoid(z2);
    }
    __syncthreads();              // the ONLY block barrier

    // ---- -W1 into regs (broadcast LDS.64) ----
    u64 w1r[7];
    #pragma unroll
    for (int d = 0; d < 7; d++)
        w1r[d] = *reinterpret_cast<const u64*>(&w1s[d][sub * 2]);

    float* optr = out + (size_t)brow0 * P_TOT + pbase + sub * 2;

    compute_tile(nx, w1r, w2s, sub, optr);
    compute_tile(ny, w1r, w2s, sub, optr + (size_t)32 * P_TOT);
}

extern "C" void kernel_launch(void* const* d_in, const int* in_sizes, int n_in,
                              void* d_out, int out_size) {
    const float* x  = (const float*)d_in[0];
    const float* t0 = (const float*)d_in[1];
    const float* t1 = (const float*)d_in[2];
    const float* t2 = (const float*)d_in[3];
    float* out = (float*)d_out;

    int B = in_sizes[0] / D_TOT;          // 4096
    dim3 grid(B / 64, P_TOT / 16);        // (64, 32) = 2048 blocks
    box_diamond_kernel<<<grid, NTH>>>(x, t0, t1, t2, out);
}